// round 1
// baseline (speedup 1.0000x reference)
#include <cuda_runtime.h>

typedef unsigned long long ull;

#define N_REC   200
#define N_INP   10
#define BATCH   256
#define TSTEPS  1000
#define TOTAL_ELEMS 51200000u   // T*B*N

// drive[t][b][r] = { inp_term(t,b,r),  0.01f * normal(t,b,r) }
static __device__ float2 g_drive[TOTAL_ELEMS];

// ---------------------------------------------------------------------------
// helpers
// ---------------------------------------------------------------------------
__device__ __forceinline__ ull ffma2(ull a, ull b, ull c) {
    ull d;
    asm("fma.rn.f32x2 %0, %1, %2, %3;" : "=l"(d) : "l"(a), "l"(b), "l"(c));
    return d;
}
__device__ __forceinline__ float lo32f(ull v) { return __uint_as_float((unsigned)v); }
__device__ __forceinline__ float hi32f(ull v) { return __uint_as_float((unsigned)(v >> 32)); }

__device__ __forceinline__ unsigned rotl32(unsigned v, int s) {
    return __funnelshift_l(v, v, s);
}

// Threefry-2x32/20 with key = (0, 42)  [jax.random.key(42)],
// partitionable scheme: counter = (hi=0, lo=p), 32-bit output = y0 ^ y1.
__device__ __forceinline__ unsigned threefry_bits(unsigned p) {
    const unsigned k0 = 0u;
    const unsigned k1 = 42u;
    const unsigned k2 = 0x1BD11BDAu ^ 0u ^ 42u;
    unsigned x0 = 0u + k0;
    unsigned x1 = p + k1;
#define TFR(rr) { x0 += x1; x1 = rotl32(x1, rr); x1 ^= x0; }
    TFR(13) TFR(15) TFR(26) TFR(6)   x0 += k1; x1 += k2 + 1u;
    TFR(17) TFR(29) TFR(16) TFR(24)  x0 += k2; x1 += k0 + 2u;
    TFR(13) TFR(15) TFR(26) TFR(6)   x0 += k0; x1 += k1 + 3u;
    TFR(17) TFR(29) TFR(16) TFR(24)  x0 += k1; x1 += k2 + 4u;
    TFR(13) TFR(15) TFR(26) TFR(6)   x0 += k2; x1 += k0 + 5u;
#undef TFR
    return x0 ^ x1;
}

// ---------------------------------------------------------------------------
// Pre-kernel: generate drive[t][b][r] = (x[b,t,:]·W_inp[r,:] + b_rec[r],
//                                        0.01 * N(0,1) matching jax key 42)
// ---------------------------------------------------------------------------
__global__ void gen_drive_kernel(const float* __restrict__ x,
                                 const float* __restrict__ W_inp,
                                 const float* __restrict__ b_rec) {
    unsigned p = blockIdx.x * blockDim.x + threadIdx.x;
    if (p >= TOTAL_ELEMS) return;

    // ---- noise: jax.random.normal(key(42), (T,B,N))[linear p] ----
    unsigned bits = threefry_bits(p);
    float f = __uint_as_float((bits >> 9) | 0x3f800000u) - 1.0f;   // [0,1)
    const float lo = __uint_as_float(0xbf7fffffu);                 // nextafter(-1,0)
    float u = fmaf(f, 2.0f, lo);                                   // (hi-lo) rounds to 2.0f
    u = fmaxf(u, lo);
    float n = __uint_as_float(0x3fb504f3u) * erfinvf(u);           // sqrt(2)_f32 * erfinv

    // ---- input drive ----
    unsigned r  = p % 200u;
    unsigned bt = p / 200u;
    unsigned b  = bt & 255u;
    unsigned t  = bt >> 8;
    const float* xr = x + (b * (unsigned)TSTEPS + t) * (unsigned)N_INP;
    const float* wr = W_inp + r * (unsigned)N_INP;
    float inp = __ldg(b_rec + r);
#pragma unroll
    for (int i = 0; i < N_INP; ++i)
        inp = fmaf(__ldg(xr + i), __ldg(wr + i), inp);

    g_drive[p] = make_float2(inp, 0.01f * n);
}

// ---------------------------------------------------------------------------
// Main persistent RNN kernel: 128 blocks x 448 threads.
// Thread (tid) = (r = tid>>1, khalf = tid&1). Each thread holds
// W_rec[r, khalf*100 .. +100) in 100 registers (50 packed f32x2).
// Block owns batch rows b0 = 2*blockIdx, b0+1. One __syncthreads per step,
// double-buffered h in SMEM.
// ---------------------------------------------------------------------------
__global__ __launch_bounds__(448, 1)
void rnn_kernel(const float* __restrict__ h0,
                const float* __restrict__ Wrec,
                float* __restrict__ out) {
    __shared__ __align__(16) float hs[2][2][224];   // [buf][batch-in-pair][r padded]

    const int tid = threadIdx.x;
    const int r   = tid >> 1;
    const int kh  = tid & 1;
    const int b0  = blockIdx.x * 2;
    const bool act = (r < N_REC);
    const int rc  = act ? r : (N_REC - 1);

    // ---- load W_rec slice into registers as f32x2 pairs ----
    ull w[50];
    if (act) {
        const ulonglong2* wp =
            reinterpret_cast<const ulonglong2*>(Wrec + r * N_REC + kh * 100);
#pragma unroll
        for (int j = 0; j < 25; ++j) {
            ulonglong2 v = wp[j];
            w[2 * j]     = v.x;
            w[2 * j + 1] = v.y;
        }
    } else {
#pragma unroll
        for (int j = 0; j < 50; ++j) w[j] = 0ull;
    }

    // ---- init h state ----
    float hold0 = 0.f, hold1 = 0.f;
    float2 dr0 = make_float2(0.f, 0.f), dr1 = make_float2(0.f, 0.f);
    if (kh == 0) {
        hold0 = act ? h0[(b0 + 0) * N_REC + r] : 0.f;
        hold1 = act ? h0[(b0 + 1) * N_REC + r] : 0.f;
        hs[0][0][r] = hold0;
        hs[0][1][r] = hold1;
        // prefetch drive for t = 0
        dr0 = g_drive[(0u * BATCH + (unsigned)b0)       * (unsigned)N_REC + (unsigned)rc];
        dr1 = g_drive[(0u * BATCH + (unsigned)(b0 + 1)) * (unsigned)N_REC + (unsigned)rc];
    }
    __syncthreads();

    const int base = kh * 100;
    float* outp0 = out + (size_t)(b0 + 0) * (TSTEPS * N_REC) + r;
    float* outp1 = out + (size_t)(b0 + 1) * (TSTEPS * N_REC) + r;

    int p = 0;
    for (int t = 0; t < TSTEPS; ++t) {
        const ulonglong2* ha = reinterpret_cast<const ulonglong2*>(&hs[p][0][base]);
        const ulonglong2* hb = reinterpret_cast<const ulonglong2*>(&hs[p][1][base]);
        ull acc0 = 0ull, acc1 = 0ull;
#pragma unroll
        for (int j = 0; j < 25; ++j) {
            ulonglong2 va = ha[j];
            ulonglong2 vb = hb[j];
            acc0 = ffma2(w[2 * j],     va.x, acc0);
            acc0 = ffma2(w[2 * j + 1], va.y, acc0);
            acc1 = ffma2(w[2 * j],     vb.x, acc1);
            acc1 = ffma2(w[2 * j + 1], vb.y, acc1);
        }
        float s0 = lo32f(acc0) + hi32f(acc0);
        float s1 = lo32f(acc1) + hi32f(acc1);
        s0 += __shfl_xor_sync(0xffffffffu, s0, 1);
        s1 += __shfl_xor_sync(0xffffffffu, s1, 1);

        if (kh == 0) {
            float rate0 = tanhf(s0 + dr0.x);
            float rate1 = tanhf(s1 + dr1.x);
            // h + alpha * ((rate - h) + eta)
            hold0 = fmaf(0.1f, (rate0 - hold0) + dr0.y, hold0);
            hold1 = fmaf(0.1f, (rate1 - hold1) + dr1.y, hold1);
            hs[p ^ 1][0][r] = hold0;
            hs[p ^ 1][1][r] = hold1;
            if (act) {
                outp0[t * N_REC] = hold0;
                outp1[t * N_REC] = hold1;
            }
            // prefetch drive for next step (latency hidden under next inner loop)
            unsigned tn = (t < TSTEPS - 1) ? (unsigned)(t + 1) : (unsigned)(TSTEPS - 1);
            dr0 = g_drive[(tn * BATCH + (unsigned)b0)       * (unsigned)N_REC + (unsigned)rc];
            dr1 = g_drive[(tn * BATCH + (unsigned)(b0 + 1)) * (unsigned)N_REC + (unsigned)rc];
        }
        p ^= 1;
        __syncthreads();
    }
}

// ---------------------------------------------------------------------------
extern "C" void kernel_launch(void* const* d_in, const int* in_sizes, int n_in,
                              void* d_out, int out_size) {
    const float* x     = (const float*)d_in[0];   // [256,1000,10]
    const float* h0    = (const float*)d_in[1];   // [256,200]
    const float* W_inp = (const float*)d_in[2];   // [200,10]
    const float* W_rec = (const float*)d_in[3];   // [200,200]
    const float* b_rec = (const float*)d_in[4];   // [200]
    float* out = (float*)d_out;                   // [256,1000,200]

    gen_drive_kernel<<<TOTAL_ELEMS / 256u, 256>>>(x, W_inp, b_rec);
    rnn_kernel<<<BATCH / 2, 448>>>(h0, W_rec, out);
}

// round 3
// speedup vs baseline: 1.0341x; 1.0341x over previous
#include <cuda_runtime.h>

typedef unsigned long long ull;

#define N_REC   200
#define N_INP   10
#define BATCH   256
#define TSTEPS  1000
#define TOTAL_ELEMS 51200000u   // T*B*N

// drive[t][b][r] = { inp_term(t,b,r),  0.01f * normal(t,b,r) }
static __device__ float2 g_drive[TOTAL_ELEMS];

// ---------------------------------------------------------------------------
// helpers
// ---------------------------------------------------------------------------
__device__ __forceinline__ ull ffma2(ull a, ull b, ull c) {
    ull d;
    asm("fma.rn.f32x2 %0, %1, %2, %3;" : "=l"(d) : "l"(a), "l"(b), "l"(c));
    return d;
}
__device__ __forceinline__ float lo32f(ull v) { return __uint_as_float((unsigned)v); }
__device__ __forceinline__ float hi32f(ull v) { return __uint_as_float((unsigned)(v >> 32)); }

__device__ __forceinline__ unsigned rotl32(unsigned v, int s) {
    return __funnelshift_l(v, v, s);
}

// Threefry-2x32/20 with key = (0, 42)  [jax.random.key(42)],
// partitionable scheme: counter = (hi=0, lo=p), 32-bit output = y0 ^ y1.
__device__ __forceinline__ unsigned threefry_bits(unsigned p) {
    const unsigned k0 = 0u;
    const unsigned k1 = 42u;
    const unsigned k2 = 0x1BD11BDAu ^ 0u ^ 42u;
    unsigned x0 = 0u + k0;
    unsigned x1 = p + k1;
#define TFR(rr) { x0 += x1; x1 = rotl32(x1, rr); x1 ^= x0; }
    TFR(13) TFR(15) TFR(26) TFR(6)   x0 += k1; x1 += k2 + 1u;
    TFR(17) TFR(29) TFR(16) TFR(24)  x0 += k2; x1 += k0 + 2u;
    TFR(13) TFR(15) TFR(26) TFR(6)   x0 += k0; x1 += k1 + 3u;
    TFR(17) TFR(29) TFR(16) TFR(24)  x0 += k1; x1 += k2 + 4u;
    TFR(13) TFR(15) TFR(26) TFR(6)   x0 += k2; x1 += k0 + 5u;
#undef TFR
    return x0 ^ x1;
}

// ---------------------------------------------------------------------------
// Pre-kernel: drive[t][b][r] = (x[b,t,:]·W_inp[r,:] + b_rec[r], 0.01*N(0,1))
// ---------------------------------------------------------------------------
__global__ void gen_drive_kernel(const float* __restrict__ x,
                                 const float* __restrict__ W_inp,
                                 const float* __restrict__ b_rec) {
    unsigned p = blockIdx.x * blockDim.x + threadIdx.x;
    if (p >= TOTAL_ELEMS) return;

    unsigned bits = threefry_bits(p);
    float f = __uint_as_float((bits >> 9) | 0x3f800000u) - 1.0f;   // [0,1)
    const float lo = __uint_as_float(0xbf7fffffu);                 // nextafter(-1,0)
    float u = fmaf(f, 2.0f, lo);
    u = fmaxf(u, lo);
    float n = __uint_as_float(0x3fb504f3u) * erfinvf(u);           // sqrt(2)*erfinv

    unsigned r  = p % 200u;
    unsigned bt = p / 200u;
    unsigned b  = bt & 255u;
    unsigned t  = bt >> 8;
    const float* xr = x + (b * (unsigned)TSTEPS + t) * (unsigned)N_INP;
    const float* wr = W_inp + r * (unsigned)N_INP;
    float inp = __ldg(b_rec + r);
#pragma unroll
    for (int i = 0; i < N_INP; ++i)
        inp = fmaf(__ldg(xr + i), __ldg(wr + i), inp);

    g_drive[p] = make_float2(inp, 0.01f * n);
}

// ---------------------------------------------------------------------------
// Main persistent RNN kernel: 128 blocks x 416 threads (13 warps -> ~157 reg cap).
// Thread = (r = tid>>1, khalf = tid&1); holds W_rec[r, kh*100..+100) in 100 regs.
// Manual depth-2 LDS pipeline + 4 split accumulators to hide LDS/FFMA latency.
// ---------------------------------------------------------------------------
__global__ __launch_bounds__(416, 1)
void rnn_kernel(const float* __restrict__ h0,
                const float* __restrict__ Wrec,
                float* __restrict__ out) {
    __shared__ __align__(16) float hs[2][2][224];   // [buf][row-in-pair][r padded]

    const int tid = threadIdx.x;
    const int r   = tid >> 1;     // 0..207
    const int kh  = tid & 1;
    const int b0  = blockIdx.x * 2;
    const bool act = (r < N_REC);
    const int rc  = act ? r : (N_REC - 1);

    // ---- W_rec slice into registers as f32x2 pairs ----
    ull w[50];
    if (act) {
        const ulonglong2* wp =
            reinterpret_cast<const ulonglong2*>(Wrec + r * N_REC + kh * 100);
#pragma unroll
        for (int j = 0; j < 25; ++j) {
            ulonglong2 v = wp[j];
            w[2 * j]     = v.x;
            w[2 * j + 1] = v.y;
        }
    } else {
#pragma unroll
        for (int j = 0; j < 50; ++j) w[j] = 0ull;
    }

    // ---- init h state ----
    float hold0 = 0.f, hold1 = 0.f;
    float2 dr0 = make_float2(0.f, 0.f), dr1 = make_float2(0.f, 0.f);
    if (kh == 0) {
        hold0 = act ? h0[(b0 + 0) * N_REC + r] : 0.f;
        hold1 = act ? h0[(b0 + 1) * N_REC + r] : 0.f;
        hs[0][0][r] = hold0;
        hs[0][1][r] = hold1;
        dr0 = g_drive[((unsigned)b0)     * (unsigned)N_REC + (unsigned)rc];
        dr1 = g_drive[((unsigned)b0 + 1u)* (unsigned)N_REC + (unsigned)rc];
    }
    __syncthreads();

    const int base = kh * 100;
    float* outp0 = out + (size_t)(b0 + 0) * (TSTEPS * N_REC) + r;
    float* outp1 = out + (size_t)(b0 + 1) * (TSTEPS * N_REC) + r;

    int p = 0;
    for (int t = 0; t < TSTEPS; ++t) {
        const ulonglong2* ha = reinterpret_cast<const ulonglong2*>(&hs[p][0][base]);
        const ulonglong2* hb = reinterpret_cast<const ulonglong2*>(&hs[p][1][base]);

        // depth-2 software pipeline over j = 0..24
        ulonglong2 va[2], vb[2];
        va[0] = ha[0]; vb[0] = hb[0];
        va[1] = ha[1]; vb[1] = hb[1];

        ull a0 = 0ull, a1 = 0ull, c0 = 0ull, c1 = 0ull;
#pragma unroll
        for (int j = 0; j < 25; ++j) {
            ulonglong2 ca = va[j & 1];
            ulonglong2 cb = vb[j & 1];
            if (j + 2 < 25) {
                va[j & 1] = ha[j + 2];
                vb[j & 1] = hb[j + 2];
            }
            a0 = ffma2(w[2 * j],     ca.x, a0);
            a1 = ffma2(w[2 * j + 1], ca.y, a1);
            c0 = ffma2(w[2 * j],     cb.x, c0);
            c1 = ffma2(w[2 * j + 1], cb.y, c1);
        }
        float s0 = (lo32f(a0) + hi32f(a0)) + (lo32f(a1) + hi32f(a1));
        float s1 = (lo32f(c0) + hi32f(c0)) + (lo32f(c1) + hi32f(c1));
        s0 += __shfl_xor_sync(0xffffffffu, s0, 1);
        s1 += __shfl_xor_sync(0xffffffffu, s1, 1);

        if (kh == 0) {
            float rate0 = tanhf(s0 + dr0.x);
            float rate1 = tanhf(s1 + dr1.x);
            hold0 = fmaf(0.1f, (rate0 - hold0) + dr0.y, hold0);
            hold1 = fmaf(0.1f, (rate1 - hold1) + dr1.y, hold1);
            hs[p ^ 1][0][r] = hold0;
            hs[p ^ 1][1][r] = hold1;
            if (act) {
                outp0[t * N_REC] = hold0;
                outp1[t * N_REC] = hold1;
            }
            unsigned tn = (t < TSTEPS - 1) ? (unsigned)(t + 1) : (unsigned)(TSTEPS - 1);
            dr0 = g_drive[(tn * BATCH + (unsigned)b0)      * (unsigned)N_REC + (unsigned)rc];
            dr1 = g_drive[(tn * BATCH + (unsigned)b0 + 1u) * (unsigned)N_REC + (unsigned)rc];
        }
        p ^= 1;
        __syncthreads();
    }
}

// ---------------------------------------------------------------------------
extern "C" void kernel_launch(void* const* d_in, const int* in_sizes, int n_in,
                              void* d_out, int out_size) {
    const float* x     = (const float*)d_in[0];   // [256,1000,10]
    const float* h0    = (const float*)d_in[1];   // [256,200]
    const float* W_inp = (const float*)d_in[2];   // [200,10]
    const float* W_rec = (const float*)d_in[3];   // [200,200]
    const float* b_rec = (const float*)d_in[4];   // [200]
    float* out = (float*)d_out;                   // [256,1000,200]

    gen_drive_kernel<<<TOTAL_ELEMS / 256u, 256>>>(x, W_inp, b_rec);
    rnn_kernel<<<BATCH / 2, 416>>>(h0, W_rec, out);
}

// round 4
// speedup vs baseline: 1.0429x; 1.0084x over previous
#include <cuda_runtime.h>

typedef unsigned long long ull;

#define N_REC   200
#define N_INP   10
#define BATCH   256
#define TSTEPS  1000
#define TOTAL_ELEMS 51200000u   // T*B*N

// drive[t][b][r] = { inp_term(t,b,r),  0.01f * normal(t,b,r) }
static __device__ float2 g_drive[TOTAL_ELEMS];

// ---------------------------------------------------------------------------
// helpers
// ---------------------------------------------------------------------------
__device__ __forceinline__ ull ffma2(ull a, ull b, ull c) {
    ull d;
    asm("fma.rn.f32x2 %0, %1, %2, %3;" : "=l"(d) : "l"(a), "l"(b), "l"(c));
    return d;
}
__device__ __forceinline__ float lo32f(ull v) { return __uint_as_float((unsigned)v); }
__device__ __forceinline__ float hi32f(ull v) { return __uint_as_float((unsigned)(v >> 32)); }

__device__ __forceinline__ unsigned rotl32(unsigned v, int s) {
    return __funnelshift_l(v, v, s);
}

// Threefry-2x32/20 with key = (0, 42)  [jax.random.key(42)],
// partitionable scheme: counter = (hi=0, lo=p), 32-bit output = y0 ^ y1.
__device__ __forceinline__ unsigned threefry_bits(unsigned p) {
    const unsigned k0 = 0u;
    const unsigned k1 = 42u;
    const unsigned k2 = 0x1BD11BDAu ^ 0u ^ 42u;
    unsigned x0 = 0u + k0;
    unsigned x1 = p + k1;
#define TFR(rr) { x0 += x1; x1 = rotl32(x1, rr); x1 ^= x0; }
    TFR(13) TFR(15) TFR(26) TFR(6)   x0 += k1; x1 += k2 + 1u;
    TFR(17) TFR(29) TFR(16) TFR(24)  x0 += k2; x1 += k0 + 2u;
    TFR(13) TFR(15) TFR(26) TFR(6)   x0 += k0; x1 += k1 + 3u;
    TFR(17) TFR(29) TFR(16) TFR(24)  x0 += k1; x1 += k2 + 4u;
    TFR(13) TFR(15) TFR(26) TFR(6)   x0 += k2; x1 += k0 + 5u;
#undef TFR
    return x0 ^ x1;
}

// ---------------------------------------------------------------------------
// Pre-kernel: drive[t][b][r] = (x[b,t,:]·W_inp[r,:] + b_rec[r], 0.01*N(0,1))
// ---------------------------------------------------------------------------
__global__ void gen_drive_kernel(const float* __restrict__ x,
                                 const float* __restrict__ W_inp,
                                 const float* __restrict__ b_rec) {
    unsigned p = blockIdx.x * blockDim.x + threadIdx.x;
    if (p >= TOTAL_ELEMS) return;

    unsigned bits = threefry_bits(p);
    float f = __uint_as_float((bits >> 9) | 0x3f800000u) - 1.0f;   // [0,1)
    const float lo = __uint_as_float(0xbf7fffffu);                 // nextafter(-1,0)
    float u = fmaf(f, 2.0f, lo);
    u = fmaxf(u, lo);
    float n = __uint_as_float(0x3fb504f3u) * erfinvf(u);           // sqrt(2)*erfinv

    unsigned r  = p % 200u;
    unsigned bt = p / 200u;
    unsigned b  = bt & 255u;
    unsigned t  = bt >> 8;
    const float* xr = x + (b * (unsigned)TSTEPS + t) * (unsigned)N_INP;
    const float* wr = W_inp + r * (unsigned)N_INP;
    float inp = __ldg(b_rec + r);
#pragma unroll
    for (int i = 0; i < N_INP; ++i)
        inp = fmaf(__ldg(xr + i), __ldg(wr + i), inp);

    g_drive[p] = make_float2(inp, 0.01f * n);
}

// ---------------------------------------------------------------------------
// Main persistent RNN kernel: 128 blocks x 416 threads (13 warps -> ~157 reg cap).
// Thread = (r = tid>>1, khalf = tid&1); holds W_rec[r, kh*100..+100) in 100 regs.
// Manual depth-2 LDS pipeline + 4 split accumulators to hide LDS/FFMA latency.
// ---------------------------------------------------------------------------
__global__ __launch_bounds__(416, 1)
void rnn_kernel(const float* __restrict__ h0,
                const float* __restrict__ Wrec,
                float* __restrict__ out) {
    __shared__ __align__(16) float hs[2][2][224];   // [buf][row-in-pair][r padded]

    const int tid = threadIdx.x;
    const int r   = tid >> 1;     // 0..207
    const int kh  = tid & 1;
    const int b0  = blockIdx.x * 2;
    const bool act = (r < N_REC);
    const int rc  = act ? r : (N_REC - 1);

    // ---- W_rec slice into registers as f32x2 pairs ----
    ull w[50];
    if (act) {
        const ulonglong2* wp =
            reinterpret_cast<const ulonglong2*>(Wrec + r * N_REC + kh * 100);
#pragma unroll
        for (int j = 0; j < 25; ++j) {
            ulonglong2 v = wp[j];
            w[2 * j]     = v.x;
            w[2 * j + 1] = v.y;
        }
    } else {
#pragma unroll
        for (int j = 0; j < 50; ++j) w[j] = 0ull;
    }

    // ---- init h state ----
    float hold0 = 0.f, hold1 = 0.f;
    float2 dr0 = make_float2(0.f, 0.f), dr1 = make_float2(0.f, 0.f);
    if (kh == 0) {
        hold0 = act ? h0[(b0 + 0) * N_REC + r] : 0.f;
        hold1 = act ? h0[(b0 + 1) * N_REC + r] : 0.f;
        hs[0][0][r] = hold0;
        hs[0][1][r] = hold1;
        dr0 = g_drive[((unsigned)b0)     * (unsigned)N_REC + (unsigned)rc];
        dr1 = g_drive[((unsigned)b0 + 1u)* (unsigned)N_REC + (unsigned)rc];
    }
    __syncthreads();

    const int base = kh * 100;
    float* outp0 = out + (size_t)(b0 + 0) * (TSTEPS * N_REC) + r;
    float* outp1 = out + (size_t)(b0 + 1) * (TSTEPS * N_REC) + r;

    int p = 0;
    for (int t = 0; t < TSTEPS; ++t) {
        const ulonglong2* ha = reinterpret_cast<const ulonglong2*>(&hs[p][0][base]);
        const ulonglong2* hb = reinterpret_cast<const ulonglong2*>(&hs[p][1][base]);

        // depth-2 software pipeline over j = 0..24
        ulonglong2 va[2], vb[2];
        va[0] = ha[0]; vb[0] = hb[0];
        va[1] = ha[1]; vb[1] = hb[1];

        ull a0 = 0ull, a1 = 0ull, c0 = 0ull, c1 = 0ull;
#pragma unroll
        for (int j = 0; j < 25; ++j) {
            ulonglong2 ca = va[j & 1];
            ulonglong2 cb = vb[j & 1];
            if (j + 2 < 25) {
                va[j & 1] = ha[j + 2];
                vb[j & 1] = hb[j + 2];
            }
            a0 = ffma2(w[2 * j],     ca.x, a0);
            a1 = ffma2(w[2 * j + 1], ca.y, a1);
            c0 = ffma2(w[2 * j],     cb.x, c0);
            c1 = ffma2(w[2 * j + 1], cb.y, c1);
        }
        float s0 = (lo32f(a0) + hi32f(a0)) + (lo32f(a1) + hi32f(a1));
        float s1 = (lo32f(c0) + hi32f(c0)) + (lo32f(c1) + hi32f(c1));
        s0 += __shfl_xor_sync(0xffffffffu, s0, 1);
        s1 += __shfl_xor_sync(0xffffffffu, s1, 1);

        if (kh == 0) {
            float rate0 = tanhf(s0 + dr0.x);
            float rate1 = tanhf(s1 + dr1.x);
            hold0 = fmaf(0.1f, (rate0 - hold0) + dr0.y, hold0);
            hold1 = fmaf(0.1f, (rate1 - hold1) + dr1.y, hold1);
            hs[p ^ 1][0][r] = hold0;
            hs[p ^ 1][1][r] = hold1;
            if (act) {
                outp0[t * N_REC] = hold0;
                outp1[t * N_REC] = hold1;
            }
            unsigned tn = (t < TSTEPS - 1) ? (unsigned)(t + 1) : (unsigned)(TSTEPS - 1);
            dr0 = g_drive[(tn * BATCH + (unsigned)b0)      * (unsigned)N_REC + (unsigned)rc];
            dr1 = g_drive[(tn * BATCH + (unsigned)b0 + 1u) * (unsigned)N_REC + (unsigned)rc];
        }
        p ^= 1;
        __syncthreads();
    }
}

// ---------------------------------------------------------------------------
extern "C" void kernel_launch(void* const* d_in, const int* in_sizes, int n_in,
                              void* d_out, int out_size) {
    const float* x     = (const float*)d_in[0];   // [256,1000,10]
    const float* h0    = (const float*)d_in[1];   // [256,200]
    const float* W_inp = (const float*)d_in[2];   // [200,10]
    const float* W_rec = (const float*)d_in[3];   // [200,200]
    const float* b_rec = (const float*)d_in[4];   // [200]
    float* out = (float*)d_out;                   // [256,1000,200]

    gen_drive_kernel<<<TOTAL_ELEMS / 256u, 256>>>(x, W_inp, b_rec);
    rnn_kernel<<<BATCH / 2, 416>>>(h0, W_rec, out);
}